// round 1
// baseline (speedup 1.0000x reference)
#include <cuda_runtime.h>

#define NN 16
#define CC 64
#define OO 64
#define HH 128
#define WW 128
#define KH 16
#define KW 16
#define HO 113
#define WO 113

#define OT 8    // outputs (o) per thread
#define WT 4    // outputs (w) per thread
#define TILE 32 // spatial tile (h and w)

// Scratch (device globals: no allocation allowed in kernel_launch)
__device__ float g_ny [OO*CC*KH*KW];   // normalized y, [o][c][kh*16+kw]
__device__ float g_S  [NN*HH*WW];      // sum_c x^2
__device__ float g_T  [NN*HH*WW];      // box-filtered in w
__device__ float g_inv[NN*HO*WO];      // 1/||x_window||

// ---------------- y normalization ----------------
__global__ void k_norm_y(const float* __restrict__ y) {
    int o = blockIdx.x;
    int tid = threadIdx.x;
    const float* yo = y + o * (CC*KH*KW);
    float s = 0.f;
    for (int i = tid; i < CC*KH*KW; i += 256) { float v = yo[i]; s += v * v; }
    __shared__ float red[256];
    red[tid] = s; __syncthreads();
    for (int st = 128; st > 0; st >>= 1) {
        if (tid < st) red[tid] += red[tid + st];
        __syncthreads();
    }
    float rinv = rsqrtf(red[0]);
    for (int i = tid; i < CC*KH*KW; i += 256)
        g_ny[o * (CC*KH*KW) + i] = yo[i] * rinv;
}

// ---------------- sum over channels of x^2 ----------------
__global__ void k_xsq(const float* __restrict__ x) {
    int idx = blockIdx.x * 256 + threadIdx.x;   // over NN*HH*WW
    int n = idx >> 14;           // / (128*128)
    int p = idx & 16383;
    const float* xp = x + n * (CC*HH*WW) + p;
    float s = 0.f;
    #pragma unroll 8
    for (int c = 0; c < CC; c++) { float v = xp[c * (HH*WW)]; s += v * v; }
    g_S[idx] = s;
}

// ---------------- box filter in w (16 wide) ----------------
__global__ void k_boxw() {
    int b = blockIdx.x;          // n*128 + h
    __shared__ float row[WW];
    row[threadIdx.x] = g_S[b * WW + threadIdx.x];
    __syncthreads();
    int w = threadIdx.x;
    if (w < WO) {
        float s = 0.f;
        #pragma unroll
        for (int k = 0; k < KW; k++) s += row[w + k];
        g_T[b * WW + w] = s;
    }
}

// ---------------- box filter in h (16 tall) + rsqrt ----------------
__global__ void k_boxh() {
    int idx = blockIdx.x * 256 + threadIdx.x;
    if (idx >= NN*HO*WO) return;
    int n = idx / (HO*WO);
    int r = idx % (HO*WO);
    int h = r / WO, w = r % WO;
    float s = 0.f;
    #pragma unroll
    for (int k = 0; k < KH; k++) s += g_T[(n * HH + h + k) * WW + w];
    g_inv[idx] = rsqrtf(s);
}

// ---------------- main conv (implicit GEMM, CUDA cores) ----------------
// grid: (16 spatial tiles, 8 o-chunks, 16 n); block: 256 threads
// thread (tx in [0,8), ty in [0,32)) -> outputs h = h0+ty, w = w0+4*tx..+3, o = o0..o0+7
__global__ __launch_bounds__(256, 2) void k_conv(const float* __restrict__ x,
                                                 float* __restrict__ out) {
    __shared__ float xs[47 * 48];     // x patch: rows h0..h0+46, cols w0..w0+47
    __shared__ float ys[OT * 256];    // 8 kernels x 256 taps for current channel

    int tid = threadIdx.x;
    int tx = tid & 7, ty = tid >> 3;
    int tile = blockIdx.x;
    int o0 = blockIdx.y * OT;
    int n  = blockIdx.z;
    int h0 = (tile >> 2) * TILE;
    int w0 = (tile & 3) * TILE;

    float acc[OT][WT];
    #pragma unroll
    for (int o = 0; o < OT; o++)
        #pragma unroll
        for (int j = 0; j < WT; j++) acc[o][j] = 0.f;

    const float* xn = x + n * (CC*HH*WW);

    for (int c = 0; c < CC; c++) {
        __syncthreads();
        // x patch: 47 rows x 12 float4 (zero-fill out of bounds; w0,128 both %4==0)
        for (int i = tid; i < 47 * 12; i += 256) {
            int r = i / 12, c4 = i % 12;
            int gh = h0 + r, gw = w0 + c4 * 4;
            float4 v = make_float4(0.f, 0.f, 0.f, 0.f);
            if (gh < HH && gw < WW)
                v = *(const float4*)(xn + (c * HH + gh) * WW + gw);
            *(float4*)(xs + r * 48 + c4 * 4) = v;
        }
        // y taps: 8 x 64 float4
        for (int i = tid; i < OT * 64; i += 256) {
            int o = i >> 6, k4 = i & 63;
            *(float4*)(ys + o * 256 + k4 * 4) =
                *(const float4*)(g_ny + ((o0 + o) * CC + c) * 256 + k4 * 4);
        }
        __syncthreads();

        #pragma unroll 1
        for (int kh = 0; kh < KH; kh++) {
            // sliding x window for this thread: 20 values (covers kw+j up to 18)
            float xw[20];
            const float* xrow = xs + (ty + kh) * 48 + 4 * tx;
            #pragma unroll
            for (int m2 = 0; m2 < 5; m2++) {
                float4 v = *(const float4*)(xrow + 4 * m2);
                xw[4*m2+0] = v.x; xw[4*m2+1] = v.y;
                xw[4*m2+2] = v.z; xw[4*m2+3] = v.w;
            }
            #pragma unroll
            for (int m = 0; m < 4; m++) {        // kw quads
                #pragma unroll
                for (int o = 0; o < OT; o++) {
                    float4 yv = *(const float4*)(ys + o * 256 + kh * 16 + m * 4);
                    #pragma unroll
                    for (int j = 0; j < WT; j++) {
                        acc[o][j] += xw[4*m + 0 + j] * yv.x;
                        acc[o][j] += xw[4*m + 1 + j] * yv.y;
                        acc[o][j] += xw[4*m + 2 + j] * yv.z;
                        acc[o][j] += xw[4*m + 3 + j] * yv.w;
                    }
                }
            }
        }
    }

    // epilogue: scale by 1/||x_win||, relu, store
    int h = h0 + ty, w = w0 + 4 * tx;
    if (h < HO) {
        #pragma unroll
        for (int j = 0; j < WT; j++) {
            if (w + j < WO) {
                float iv = g_inv[(n * HO + h) * WO + w + j];
                #pragma unroll
                for (int o = 0; o < OT; o++) {
                    float v = acc[o][j] * iv;
                    out[(((n * OO) + (o0 + o)) * HO + h) * WO + w + j] =
                        v > 0.f ? v : 0.f;
                }
            }
        }
    }
}

extern "C" void kernel_launch(void* const* d_in, const int* in_sizes, int n_in,
                              void* d_out, int out_size) {
    const float* x = (const float*)d_in[0];   // (16,64,128,128)
    const float* y = (const float*)d_in[1];   // (64,64,16,16)
    float* out = (float*)d_out;               // (16,64,113,113)

    k_norm_y<<<OO, 256>>>(y);
    k_xsq<<<(NN*HH*WW) / 256, 256>>>(x);
    k_boxw<<<NN * HH, WW>>>();
    k_boxh<<<(NN*HO*WO + 255) / 256, 256>>>();

    dim3 grid(16, OO / OT, NN);
    k_conv<<<grid, 256>>>(x, out);
}

// round 4
// speedup vs baseline: 1.0059x; 1.0059x over previous
#include <cuda_runtime.h>

#define NN 16
#define CC 64
#define OO 64
#define HH 128
#define WW 128
#define KH 16
#define KW 16
#define HO 113
#define WO 113

#define OT 8    // outputs (o) per thread (4 f32x2 pairs)
#define OP 4    // o-pairs per thread
#define WT 4    // outputs (w) per thread
#define TILE 32 // spatial tile (h and w)

// Scratch (device globals: no allocation allowed in kernel_launch)
__device__ float g_ny [OO*CC*KH*KW];   // normalized y, [o][c][kh*16+kw]
__device__ float g_S  [NN*HH*WW];      // sum_c x^2
__device__ float g_T  [NN*HH*WW];      // box-filtered in w
__device__ float g_inv[NN*HO*WO];      // 1/||x_window||

typedef unsigned long long ull;

__device__ __forceinline__ void ffma2(ull &acc, ull a, ull b) {
    asm("fma.rn.f32x2 %0, %1, %2, %0;" : "+l"(acc) : "l"(a), "l"(b));
}
__device__ __forceinline__ ull bcast2(float v) {
    ull r;
    asm("mov.b64 %0, {%1, %1};" : "=l"(r) : "f"(v));
    return r;
}

// ---------------- y normalization ----------------
__global__ void k_norm_y(const float* __restrict__ y) {
    int o = blockIdx.x;
    int tid = threadIdx.x;
    const float* yo = y + o * (CC*KH*KW);
    float s = 0.f;
    for (int i = tid; i < CC*KH*KW; i += 256) { float v = yo[i]; s += v * v; }
    __shared__ float red[256];
    red[tid] = s; __syncthreads();
    for (int st = 128; st > 0; st >>= 1) {
        if (tid < st) red[tid] += red[tid + st];
        __syncthreads();
    }
    float rinv = rsqrtf(red[0]);
    for (int i = tid; i < CC*KH*KW; i += 256)
        g_ny[o * (CC*KH*KW) + i] = yo[i] * rinv;
}

// ---------------- sum over channels of x^2 ----------------
__global__ void k_xsq(const float* __restrict__ x) {
    int idx = blockIdx.x * 256 + threadIdx.x;   // over NN*HH*WW
    int n = idx >> 14;           // / (128*128)
    int p = idx & 16383;
    const float* xp = x + n * (CC*HH*WW) + p;
    float s = 0.f;
    #pragma unroll 8
    for (int c = 0; c < CC; c++) { float v = xp[c * (HH*WW)]; s += v * v; }
    g_S[idx] = s;
}

// ---------------- box filter in w (16 wide) ----------------
__global__ void k_boxw() {
    int b = blockIdx.x;          // n*128 + h
    __shared__ float row[WW];
    row[threadIdx.x] = g_S[b * WW + threadIdx.x];
    __syncthreads();
    int w = threadIdx.x;
    if (w < WO) {
        float s = 0.f;
        #pragma unroll
        for (int k = 0; k < KW; k++) s += row[w + k];
        g_T[b * WW + w] = s;
    }
}

// ---------------- box filter in h (16 tall) + rsqrt ----------------
__global__ void k_boxh() {
    int idx = blockIdx.x * 256 + threadIdx.x;
    if (idx >= NN*HO*WO) return;
    int n = idx / (HO*WO);
    int r = idx % (HO*WO);
    int h = r / WO, w = r % WO;
    float s = 0.f;
    #pragma unroll
    for (int k = 0; k < KH; k++) s += g_T[(n * HH + h + k) * WW + w];
    g_inv[idx] = rsqrtf(s);
}

// ---------------- main conv (implicit GEMM, packed f32x2 FMA) ----------------
// grid: (16 spatial tiles, 8 o-chunks, 16 n); block: 256 threads
// thread (tx in [0,8), ty in [0,32)) -> h = h0+ty, w = w0+4*tx..+3, o = o0..o0+7
// Accumulators are f32x2 pairs over (even o, odd o).
__global__ __launch_bounds__(256, 2) void k_conv(const float* __restrict__ x,
                                                 float* __restrict__ out) {
    __shared__ float xs[47 * 48];      // x patch: rows h0..h0+46, cols w0..w0+47
    __shared__ float ys2[OP * 512];    // interleaved y pairs: [op][tap][2]

    int tid = threadIdx.x;
    int tx = tid & 7, ty = tid >> 3;
    int tile = blockIdx.x;
    int o0 = blockIdx.y * OT;
    int n  = blockIdx.z;
    int h0 = (tile >> 2) * TILE;
    int w0 = (tile & 3) * TILE;

    ull acc2[OP][WT];
    #pragma unroll
    for (int op = 0; op < OP; op++)
        #pragma unroll
        for (int j = 0; j < WT; j++) acc2[op][j] = 0ull;

    const float* xn = x + n * (CC*HH*WW);

    for (int c = 0; c < CC; c++) {
        __syncthreads();
        // x patch: 47 rows x 12 float4 (zero-fill out of bounds; w0,128 both %4==0)
        for (int i = tid; i < 47 * 12; i += 256) {
            int r = i / 12, c4 = i % 12;
            int gh = h0 + r, gw = w0 + c4 * 4;
            float4 v = make_float4(0.f, 0.f, 0.f, 0.f);
            if (gh < HH && gw < WW)
                v = *(const float4*)(xn + (c * HH + gh) * WW + gw);
            *(float4*)(xs + r * 48 + c4 * 4) = v;
        }
        // y taps, interleaved by o-pair: ys2[op*512 + tap*2 + {even,odd}]
        {
            int op = tid >> 6, t4 = tid & 63;     // 4 o-pairs x 64 tap-quads
            int oe = o0 + 2 * op;
            float4 a = *(const float4*)(g_ny + (oe * CC + c) * 256 + t4 * 4);
            float4 b = *(const float4*)(g_ny + ((oe + 1) * CC + c) * 256 + t4 * 4);
            float* dst = ys2 + op * 512 + t4 * 8;
            ((float2*)dst)[0] = make_float2(a.x, b.x);
            ((float2*)dst)[1] = make_float2(a.y, b.y);
            ((float2*)dst)[2] = make_float2(a.z, b.z);
            ((float2*)dst)[3] = make_float2(a.w, b.w);
        }
        __syncthreads();

        #pragma unroll 1
        for (int kh = 0; kh < KH; kh++) {
            // sliding x window for this thread, broadcast-packed once per kh:
            // covers kw + j for kw in [0,16), j in [0,4) -> 19 values
            ull xpk[19];
            const float* xrow = xs + (ty + kh) * 48 + 4 * tx;
            #pragma unroll
            for (int m2 = 0; m2 < 5; m2++) {
                float4 v = *(const float4*)(xrow + 4 * m2);
                if (4 * m2 + 0 < 19) xpk[4*m2+0] = bcast2(v.x);
                if (4 * m2 + 1 < 19) xpk[4*m2+1] = bcast2(v.y);
                if (4 * m2 + 2 < 19) xpk[4*m2+2] = bcast2(v.z);
                if (4 * m2 + 3 < 19) xpk[4*m2+3] = bcast2(v.w);
            }
            #pragma unroll
            for (int m = 0; m < 4; m++) {        // kw quads
                #pragma unroll
                for (int op = 0; op < OP; op++) {
                    const ulonglong2* yp = (const ulonglong2*)
                        (ys2 + op * 512 + (kh * 16 + m * 4) * 2);
                    ulonglong2 y01 = yp[0];   // taps t=0,1 (interleaved pairs)
                    ulonglong2 y23 = yp[1];   // taps t=2,3
                    #pragma unroll
                    for (int j = 0; j < WT; j++) {
                        ffma2(acc2[op][j], xpk[4*m + 0 + j], y01.x);
                        ffma2(acc2[op][j], xpk[4*m + 1 + j], y01.y);
                        ffma2(acc2[op][j], xpk[4*m + 2 + j], y23.x);
                        ffma2(acc2[op][j], xpk[4*m + 3 + j], y23.y);
                    }
                }
            }
        }
    }

    // epilogue: scale by 1/||x_win||, relu, store
    int h = h0 + ty, w = w0 + 4 * tx;
    if (h < HO) {
        #pragma unroll
        for (int j = 0; j < WT; j++) {
            if (w + j < WO) {
                float iv = g_inv[(n * HO + h) * WO + w + j];
                #pragma unroll
                for (int op = 0; op < OP; op++) {
                    ull v = acc2[op][j];
                    float lo = __int_as_float((int)(v & 0xffffffffull));
                    float hi = __int_as_float((int)(v >> 32));
                    float ve = lo * iv, vo = hi * iv;
                    int oe = o0 + 2 * op;
                    out[(((n * OO) + oe) * HO + h) * WO + w + j] = ve > 0.f ? ve : 0.f;
                    out[(((n * OO) + oe + 1) * HO + h) * WO + w + j] = vo > 0.f ? vo : 0.f;
                }
            }
        }
    }
}

extern "C" void kernel_launch(void* const* d_in, const int* in_sizes, int n_in,
                              void* d_out, int out_size) {
    const float* x = (const float*)d_in[0];   // (16,64,128,128)
    const float* y = (const float*)d_in[1];   // (64,64,16,16)
    float* out = (float*)d_out;               // (16,64,113,113)

    k_norm_y<<<OO, 256>>>(y);
    k_xsq<<<(NN*HH*WW) / 256, 256>>>(x);
    k_boxw<<<NN * HH, WW>>>();
    k_boxh<<<(NN*HO*WO + 255) / 256, 256>>>();

    dim3 grid(16, OO / OT, NN);
    k_conv<<<grid, 256>>>(x, out);
}

// round 8
// speedup vs baseline: 2.4095x; 2.3953x over previous
#include <cuda_runtime.h>
#include <cstdint>

#define NN 16
#define CC 64
#define OO 64
#define HH 128
#define WW 128
#define KH 16
#define KW 16
#define HO 113
#define WO 113
#define TH 4        // h rows per CTA; M = TH*128 = 512
#define RW 144      // staged row width (floats): 128 + 16 slide room, zero-padded

// ---------------- scratch globals ----------------
__device__ float g_ny [OO*CC*KH*KW];     // normalized y
__device__ float g_S  [NN*HH*WW];
__device__ float g_T  [NN*HH*WW];
__device__ float g_inv[NN*HO*WO];
__device__ uint2 g_bf [CC*KH*2*256];     // B frags: [c][kh][kwh][n8(8)][lane(32)] = 4MB

// ---------------- helpers ----------------
__device__ __forceinline__ uint32_t tf32_rna(float v) {
    uint32_t r;
    asm("cvt.rna.tf32.f32 %0, %1;" : "=r"(r) : "f"(v));
    return r;
}
__device__ __forceinline__ void mma_tf32(float* c, const uint32_t* a,
                                         uint32_t b0, uint32_t b1) {
    asm volatile(
        "mma.sync.aligned.m16n8k8.row.col.f32.tf32.tf32.f32 "
        "{%0,%1,%2,%3}, {%4,%5,%6,%7}, {%8,%9}, {%0,%1,%2,%3};"
        : "+f"(c[0]), "+f"(c[1]), "+f"(c[2]), "+f"(c[3])
        : "r"(a[0]), "r"(a[1]), "r"(a[2]), "r"(a[3]), "r"(b0), "r"(b1));
}

// ---------------- prep: normalize y ----------------
__global__ void k_norm_y(const float* __restrict__ y) {
    int o = blockIdx.x, tid = threadIdx.x;
    const float* yo = y + o * (CC*KH*KW);
    float s = 0.f;
    for (int i = tid; i < CC*KH*KW; i += 256) { float v = yo[i]; s += v * v; }
    __shared__ float red[256];
    red[tid] = s; __syncthreads();
    for (int st = 128; st > 0; st >>= 1) {
        if (tid < st) red[tid] += red[tid + st];
        __syncthreads();
    }
    float rinv = rsqrtf(red[0]);
    for (int i = tid; i < CC*KH*KW; i += 256)
        g_ny[o * (CC*KH*KW) + i] = yo[i] * rinv;
}

// ---------------- prep: precompute tf32 B fragments ----------------
// grid 2048 = (c*16+kh)*2+kwh ; block 256 = (n8, lane)
// b0 = B[k=tig][n=gid], b1 = B[k=tig+4][n=gid]; n -> o, k -> kw offset
__global__ void k_bfrag() {
    int ch = blockIdx.x;
    int kwh = ch & 1, kh = (ch >> 1) & 15, c = ch >> 5;
    int n8 = threadIdx.x >> 5, lane = threadIdx.x & 31;
    int o  = n8 * 8 + (lane >> 2);
    int k0 = kwh * 8 + (lane & 3);
    const float* yb = g_ny + o * (CC*KH*KW) + c * (KH*KW) + kh * KW;
    uint2 r;
    r.x = tf32_rna(yb[k0]);
    r.y = tf32_rna(yb[k0 + 4]);
    g_bf[ch * 256 + n8 * 32 + lane] = r;
}

// ---------------- prep: x-norm pipeline ----------------
__global__ void k_xsq(const float* __restrict__ x) {
    int idx = blockIdx.x * 256 + threadIdx.x;
    int n = idx >> 14, p = idx & 16383;
    const float* xp = x + n * (CC*HH*WW) + p;
    float s = 0.f;
    #pragma unroll 8
    for (int c = 0; c < CC; c++) { float v = xp[c * (HH*WW)]; s += v * v; }
    g_S[idx] = s;
}
__global__ void k_boxw() {
    int b = blockIdx.x;
    __shared__ float row[WW];
    row[threadIdx.x] = g_S[b * WW + threadIdx.x];
    __syncthreads();
    int w = threadIdx.x;
    if (w < WO) {
        float s = 0.f;
        #pragma unroll
        for (int k = 0; k < KW; k++) s += row[w + k];
        g_T[b * WW + w] = s;
    }
}
__global__ void k_boxh() {
    int idx = blockIdx.x * 256 + threadIdx.x;
    if (idx >= NN*HO*WO) return;
    int n = idx / (HO*WO), r = idx % (HO*WO);
    int h = r / WO, w = r % WO;
    float s = 0.f;
    #pragma unroll
    for (int k = 0; k < KH; k++) s += g_T[(n * HH + h + k) * WW + w];
    g_inv[idx] = rsqrtf(s);
}

// ---------------- main conv: tf32 mma.sync implicit GEMM ----------------
// grid (29, 16): h-tile, n. 512 threads = 16 warps.
// warp wid: wm = wid&7 -> dh = wm>>1, whalf = wm&1 ; ns = wid>>3 (o half)
// warp tile: 64 m (fixed dh, w in [whalf*64, +64)) x 32 n (o in [ns*32, +32))
__global__ __launch_bounds__(512, 1) void k_conv_mma(const float* __restrict__ x,
                                                     float* __restrict__ out) {
    __shared__ float rows[19 * RW];       // x rows h0..h0+18, tf32-rounded
    __shared__ uint2 smB[4 * 2 * 256];    // B frags for 4 kh (2 kwh each)

    int tid = threadIdx.x, lane = tid & 31, wid = tid >> 5;
    int n = blockIdx.y, h0 = blockIdx.x * TH;
    int wm = wid & 7, ns = wid >> 3;
    int dh = wm >> 1, whalf = wm & 1;
    int gid = lane >> 2, tig = lane & 3;

    float acc[4][4][4];
    #pragma unroll
    for (int mt = 0; mt < 4; mt++)
        #pragma unroll
        for (int t = 0; t < 4; t++)
            #pragma unroll
            for (int r = 0; r < 4; r++) acc[mt][t][r] = 0.f;

    const float* xn = x + n * (CC*HH*WW);

    for (int c = 0; c < CC; c++) {
        __syncthreads();                       // previous c done reading rows
        // stage 19 x-rows (tf32-rounded), zero-pad cols >= 128
        for (int i = tid; i < 19 * 36; i += 512) {
            int j = i / 36, c4 = i % 36;
            int row = h0 + j; if (row > HH - 1) row = HH - 1;
            int gw = c4 * 4;
            float4 v = make_float4(0.f, 0.f, 0.f, 0.f);
            if (gw < WW) v = *(const float4*)(xn + (c * HH + row) * WW + gw);
            uint4 tv;
            tv.x = tf32_rna(v.x); tv.y = tf32_rna(v.y);
            tv.z = tf32_rna(v.z); tv.w = tf32_rna(v.w);
            *(uint4*)(rows + j * RW + gw) = tv;
        }
        #pragma unroll 1
        for (int g = 0; g < 4; g++) {          // 4 kh per B-stage group
            __syncthreads();                   // rows ready / prev B reads done
            const uint2* src = g_bf + (c * 16 + g * 4) * 2 * 256;
            for (int i = tid; i < 2048; i += 512) smB[i] = src[i];
            __syncthreads();                   // B ready
            #pragma unroll 1
            for (int kg = 0; kg < 4; kg++) {
                const float* rbase = rows + (g * 4 + kg + dh) * RW;
                #pragma unroll
                for (int kwh = 0; kwh < 2; kwh++) {
                    uint2 bf[4];
                    const uint2* bb = smB + ((kg * 2 + kwh) * 8 + ns * 4) * 32 + lane;
                    #pragma unroll
                    for (int t = 0; t < 4; t++) bf[t] = bb[t * 32];
                    #pragma unroll
                    for (int mt = 0; mt < 4; mt++) {
                        const float* ab = rbase + whalf * 64 + mt * 16 +
                                          kwh * 8 + gid + tig;
                        uint32_t a[4];
                        a[0] = __float_as_uint(ab[0]);
                        a[1] = __float_as_uint(ab[8]);
                        a[2] = __float_as_uint(ab[4]);
                        a[3] = __float_as_uint(ab[12]);
                        #pragma unroll
                        for (int t = 0; t < 4; t++)
                            mma_tf32(acc[mt][t], a, bf[t].x, bf[t].y);
                    }
                }
            }
        }
    }

    // epilogue: scale by 1/||x_win||, relu, store
    int h = h0 + dh;
    if (h < HO) {
        const float* ivrow = g_inv + (n * HO + h) * WO;
        #pragma unroll
        for (int mt = 0; mt < 4; mt++) {
            int w0 = whalf * 64 + mt * 16 + gid;
            float iv0 = (w0 < WO)     ? ivrow[w0]     : 0.f;
            float iv8 = (w0 + 8 < WO) ? ivrow[w0 + 8] : 0.f;
            #pragma unroll
            for (int t = 0; t < 4; t++) {
                int o = ns * 32 + t * 8 + tig * 2;
                float* ob = out + ((n * OO + o) * HO + h) * WO;
                if (w0 < WO) {
                    float v0 = acc[mt][t][0] * iv0;
                    float v1 = acc[mt][t][1] * iv0;
                    ob[w0]           = v0 > 0.f ? v0 : 0.f;
                    ob[HO*WO + w0]   = v1 > 0.f ? v1 : 0.f;
                }
                if (w0 + 8 < WO) {
                    float v2 = acc[mt][t][2] * iv8;
                    float v3 = acc[mt][t][3] * iv8;
                    ob[w0 + 8]         = v2 > 0.f ? v2 : 0.f;
                    ob[HO*WO + w0 + 8] = v3 > 0.f ? v3 : 0.f;
                }
            }
        }
    }
}

extern "C" void kernel_launch(void* const* d_in, const int* in_sizes, int n_in,
                              void* d_out, int out_size) {
    const float* x = (const float*)d_in[0];   // (16,64,128,128)
    const float* y = (const float*)d_in[1];   // (64,64,16,16)
    float* out = (float*)d_out;               // (16,64,113,113)

    k_norm_y<<<OO, 256>>>(y);
    k_bfrag<<<CC*KH*2, 256>>>();
    k_xsq<<<(NN*HH*WW) / 256, 256>>>(x);
    k_boxw<<<NN * HH, WW>>>();
    k_boxh<<<(NN*HO*WO + 255) / 256, 256>>>();

    dim3 grid((HO + TH - 1) / TH, NN);
    k_conv_mma<<<grid, 512>>>(x, out);
}

// round 10
// speedup vs baseline: 4.3361x; 1.7996x over previous
#include <cuda_runtime.h>
#include <cstdint>

#define NN 16
#define CC 64
#define OO 64
#define HH 128
#define WW 128
#define KH 16
#define KW 16
#define HO 113
#define WO 113
#define TH 4        // h rows per CTA; M = TH*128 = 512
#define RW 144      // staged row width (floats): 128 + slide room, zero-padded

// ---------------- scratch globals ----------------
__device__ float g_ny [OO*CC*KH*KW];     // normalized y
__device__ float g_S  [NN*HH*WW];
__device__ float g_T  [NN*HH*WW];
__device__ float g_inv[NN*HO*WO];
__device__ uint2 g_bf [CC*KH*8*32];      // fp16 B frags: [c*16+kh][n8(8)][lane(32)] = 2MB

// ---------------- helpers ----------------
__device__ __forceinline__ uint32_t pack_h2(float hi, float lo) {
    uint32_t r;
    asm("cvt.rn.f16x2.f32 %0, %1, %2;" : "=r"(r) : "f"(hi), "f"(lo));
    return r;
}
__device__ __forceinline__ void mma_f16(float* c, uint32_t a0, uint32_t a1,
                                        uint32_t a2, uint32_t a3,
                                        uint32_t b0, uint32_t b1) {
    asm volatile(
        "mma.sync.aligned.m16n8k16.row.col.f32.f16.f16.f32 "
        "{%0,%1,%2,%3}, {%4,%5,%6,%7}, {%8,%9}, {%0,%1,%2,%3};"
        : "+f"(c[0]), "+f"(c[1]), "+f"(c[2]), "+f"(c[3])
        : "r"(a0), "r"(a1), "r"(a2), "r"(a3), "r"(b0), "r"(b1));
}

// ---------------- prep: normalize y ----------------
__global__ void k_norm_y(const float* __restrict__ y) {
    int o = blockIdx.x, tid = threadIdx.x;
    const float* yo = y + o * (CC*KH*KW);
    float s = 0.f;
    for (int i = tid; i < CC*KH*KW; i += 256) { float v = yo[i]; s += v * v; }
    __shared__ float red[256];
    red[tid] = s; __syncthreads();
    for (int st = 128; st > 0; st >>= 1) {
        if (tid < st) red[tid] += red[tid + st];
        __syncthreads();
    }
    float rinv = rsqrtf(red[0]);
    for (int i = tid; i < CC*KH*KW; i += 256)
        g_ny[o * (CC*KH*KW) + i] = yo[i] * rinv;
}

// ---------------- prep: precompute fp16 B fragments (m16n8k16) ----------------
// grid 1024 = c*16+kh ; block 256 = (n8, lane)
// b0 = {B[2tig][gid], B[2tig+1][gid]}, b1 = {B[2tig+8][gid], B[2tig+9][gid]}
// where B[k][n] = nhat_y[o = n8*8+gid][c][kh][kw = k]
__global__ void k_bfrag() {
    int ch = blockIdx.x;
    int kh = ch & 15, c = ch >> 4;
    int n8 = threadIdx.x >> 5, lane = threadIdx.x & 31;
    int gid = lane >> 2, tig = lane & 3;
    int o = n8 * 8 + gid;
    const float* yb = g_ny + o * (CC*KH*KW) + c * (KH*KW) + kh * KW;
    int k0 = 2 * tig;
    uint2 r;
    r.x = pack_h2(yb[k0 + 1], yb[k0]);
    r.y = pack_h2(yb[k0 + 9], yb[k0 + 8]);
    g_bf[(ch * 8 + n8) * 32 + lane] = r;
}

// ---------------- prep: x-norm pipeline ----------------
__global__ void k_xsq(const float* __restrict__ x) {
    int idx = blockIdx.x * 256 + threadIdx.x;
    int n = idx >> 14, p = idx & 16383;
    const float* xp = x + n * (CC*HH*WW) + p;
    float s = 0.f;
    #pragma unroll 8
    for (int c = 0; c < CC; c++) { float v = xp[c * (HH*WW)]; s += v * v; }
    g_S[idx] = s;
}
__global__ void k_boxw() {
    int b = blockIdx.x;
    __shared__ float row[WW];
    row[threadIdx.x] = g_S[b * WW + threadIdx.x];
    __syncthreads();
    int w = threadIdx.x;
    if (w < WO) {
        float s = 0.f;
        #pragma unroll
        for (int k = 0; k < KW; k++) s += row[w + k];
        g_T[b * WW + w] = s;
    }
}
__global__ void k_boxh() {
    int idx = blockIdx.x * 256 + threadIdx.x;
    if (idx >= NN*HO*WO) return;
    int n = idx / (HO*WO), r = idx % (HO*WO);
    int h = r / WO, w = r % WO;
    float s = 0.f;
    #pragma unroll
    for (int k = 0; k < KH; k++) s += g_T[(n * HH + h + k) * WW + w];
    g_inv[idx] = rsqrtf(s);
}

// ---------------- main conv: fp16 m16n8k16 implicit GEMM ----------------
// grid (29, 16): h-tile, n. 512 threads = 16 warps.
// warp wid: wm = wid&7 -> dh = wm>>1, whalf = wm&1 ; ns = wid>>3 (o half)
// warp tile: 64 m (fixed dh, w in [whalf*64, +64)) x 32 n (o in [ns*32, +32))
// K chunk = (c, kh): one k16 mma consumes all 16 kw taps.
__global__ __launch_bounds__(512, 1) void k_conv_mma(const float* __restrict__ x,
                                                     float* __restrict__ out) {
    __shared__ float rows[19 * RW];       // x rows h0..h0+18 (fp32)
    __shared__ uint2 smB[4 * 8 * 32];     // B frags for 4 kh

    int tid = threadIdx.x, lane = tid & 31, wid = tid >> 5;
    int n = blockIdx.y, h0 = blockIdx.x * TH;
    int wm = wid & 7, ns = wid >> 3;
    int dh = wm >> 1, whalf = wm & 1;
    int gid = lane >> 2, tig = lane & 3;
    int aoff = whalf * 64 + gid + 2 * tig;

    float acc[4][4][4];
    #pragma unroll
    for (int mt = 0; mt < 4; mt++)
        #pragma unroll
        for (int t = 0; t < 4; t++)
            #pragma unroll
            for (int r = 0; r < 4; r++) acc[mt][t][r] = 0.f;

    const float* xn = x + n * (CC*HH*WW);

    for (int c = 0; c < CC; c++) {
        __syncthreads();                       // previous c done reading rows
        // stage 19 x-rows (raw fp32), zero-pad cols >= 128
        for (int i = tid; i < 19 * 36; i += 512) {
            int j = i / 36, c4 = i % 36;
            int row = h0 + j; if (row > HH - 1) row = HH - 1;
            int gw = c4 * 4;
            float4 v = make_float4(0.f, 0.f, 0.f, 0.f);
            if (gw < WW) v = *(const float4*)(xn + (c * HH + row) * WW + gw);
            *(float4*)(rows + j * RW + gw) = v;
        }
        #pragma unroll 1
        for (int g = 0; g < 4; g++) {          // 4 kh per B-stage group
            __syncthreads();                   // rows ready / prev B reads done
            const uint2* src = g_bf + (c * 16 + g * 4) * 256;
            for (int i = tid; i < 1024; i += 512) smB[i] = src[i];
            __syncthreads();                   // B ready
            #pragma unroll
            for (int kg = 0; kg < 4; kg++) {
                const float* rbase = rows + (g * 4 + kg + dh) * RW + aoff;
                // Toeplitz A: 9 packed fp16 pairs cover all 4 m-tiles
                uint32_t pk[9];
                #pragma unroll
                for (int j = 0; j < 9; j++)
                    pk[j] = pack_h2(rbase[8 * j + 1], rbase[8 * j]);
                #pragma unroll
                for (int t = 0; t < 4; t++) {
                    uint2 b = smB[((kg * 8 + ns * 4 + t)) * 32 + lane];
                    #pragma unroll
                    for (int mt = 0; mt < 4; mt++)
                        mma_f16(acc[mt][t], pk[2*mt], pk[2*mt+1],
                                pk[2*mt+1], pk[2*mt+2], b.x, b.y);
                }
            }
        }
    }

    // epilogue: scale by 1/||x_win||, relu, store
    int h = h0 + dh;
    if (h < HO) {
        const float* ivrow = g_inv + (n * HO + h) * WO;
        #pragma unroll
        for (int mt = 0; mt < 4; mt++) {
            int w0 = whalf * 64 + mt * 16 + gid;
            float iv0 = (w0 < WO)     ? ivrow[w0]     : 0.f;
            float iv8 = (w0 + 8 < WO) ? ivrow[w0 + 8] : 0.f;
            #pragma unroll
            for (int t = 0; t < 4; t++) {
                int o = ns * 32 + t * 8 + tig * 2;
                float* ob = out + ((n * OO + o) * HO + h) * WO;
                if (w0 < WO) {
                    float v0 = acc[mt][t][0] * iv0;
                    float v1 = acc[mt][t][1] * iv0;
                    ob[w0]           = v0 > 0.f ? v0 : 0.f;
                    ob[HO*WO + w0]   = v1 > 0.f ? v1 : 0.f;
                }
                if (w0 + 8 < WO) {
                    float v2 = acc[mt][t][2] * iv8;
                    float v3 = acc[mt][t][3] * iv8;
                    ob[w0 + 8]         = v2 > 0.f ? v2 : 0.f;
                    ob[HO*WO + w0 + 8] = v3 > 0.f ? v3 : 0.f;
                }
            }
        }
    }
}

extern "C" void kernel_launch(void* const* d_in, const int* in_sizes, int n_in,
                              void* d_out, int out_size) {
    const float* x = (const float*)d_in[0];   // (16,64,128,128)
    const float* y = (const float*)d_in[1];   // (64,64,16,16)
    float* out = (float*)d_out;               // (16,64,113,113)

    k_norm_y<<<OO, 256>>>(y);
    k_bfrag<<<CC*KH, 256>>>();
    k_xsq<<<(NN*HH*WW) / 256, 256>>>(x);
    k_boxw<<<NN * HH, WW>>>();
    k_boxh<<<(NN*HO*WO + 255) / 256, 256>>>();

    dim3 grid((HO + TH - 1) / TH, NN);
    k_conv_mma<<<grid, 512>>>(x, out);
}